// round 7
// baseline (speedup 1.0000x reference)
#include <cuda_runtime.h>
#include <math_constants.h>

// GATv2 additive attention + masked softmax, mask-compacted v4.
// score(b,h,i,j) = sum_d a[h,d] * silu(q[b,h,i,d] + k[b,h,j,d])
// silu(s) = u*(1+tanh(u)), u=s/2; q pre-scaled by 0.5 at staging,
// k scaled inside the FMA (u = fma(0.5,k,qh)).
// Compacted j gathered DIRECTLY FROM GLOBAL (L1-resident K tile):
// no smem K staging, no bank conflicts, no block-wide barrier after staging.

#define B_   2
#define H_   8
#define LQ_  384
#define LK_  384
#define D_   64
#define ROWS 8          // q rows per block, 1 warp per row
#define PAD  68         // q smem row stride (words)
#define NC   12         // LK/32 chunks

__device__ __forceinline__ float tanh_approx(float x) {
    float r;
    asm("tanh.approx.f32 %0, %1;" : "=f"(r) : "f"(x));
    return r;
}

__global__ __launch_bounds__(256, 2)
void gatv2_kernel(const float* __restrict__ q, const float* __restrict__ k,
                  const float* __restrict__ att, const int* __restrict__ mask,
                  float* __restrict__ out)
{
    extern __shared__ float smem[];
    float* qs = smem;                    // [ROWS][PAD] (0.5*q)
    float* as = qs + ROWS * PAD;         // [D]
    float* ws = as + D_;                 // [ROWS][LK] warp-private scatter buffers
    unsigned short* idxb = (unsigned short*)(ws + ROWS * LK_);  // [ROWS][LK]

    const int ntiles = LQ_ / ROWS;       // 48
    int blk   = blockIdx.x;
    int bh    = blk / ntiles;
    int itile = blk - bh * ntiles;
    int h     = bh & (H_ - 1);
    int tid   = threadIdx.x;
    int warp  = tid >> 5, lane = tid & 31;
    int i     = itile * ROWS + warp;

    // ---- stage 0.5*q rows + a (cooperative) ----
    const float4* qg = (const float4*)(q + ((size_t)bh * LQ_ + itile * ROWS) * D_);
    for (int idxr = tid; idxr < ROWS * D_ / 4; idxr += 256) {
        int r = idxr >> 4, d4 = idxr & 15;
        float4 v = qg[idxr];
        v.x *= 0.5f; v.y *= 0.5f; v.z *= 0.5f; v.w *= 0.5f;
        *(float4*)(qs + r * PAD + d4 * 4) = v;
    }
    if (tid < D_) as[tid] = att[h * D_ + tid];

    // ---- mask ballot + compaction scatter (warp-private stripe) ----
    const int* mrow = mask + ((size_t)bh * LQ_ + i) * LK_;
    unsigned short* stripe = idxb + warp * LK_;
    int base = 0;
#pragma unroll
    for (int c = 0; c < NC; c++) {
        int j = c * 32 + lane;
        int keep = (mrow[j] == 0);
        unsigned b = __ballot_sync(0xffffffffu, keep);
        if (keep) stripe[base + __popc(b & ((1u << lane) - 1u))] = (unsigned short)j;
        base += __popc(b);
    }
    int nkeep  = base;
    int nchunk = (nkeep + 31) >> 5;

    __syncthreads();                     // q/a visible to all warps

    // ---- compacted indices to registers ----
    int jdx[NC];
#pragma unroll
    for (int cc = 0; cc < NC; cc++) {
        int slot = cc * 32 + lane;
        jdx[cc] = (slot < nkeep) ? (int)stripe[slot] : 0;
    }

    const float* qrow  = qs + warp * PAD;
    const float* kbase = k + (size_t)bh * LK_ * D_;

    float acc[NC];
#pragma unroll
    for (int cc = 0; cc < NC; cc++) acc[cc] = -CUDART_INF_F;

    // ---- chunk-pair score loop: K gathered from global (L1), d4 unrolled x4 ----
#pragma unroll
    for (int p = 0; p < NC / 2; p++) {
        if (2 * p < nchunk) {
            const float4* kr0 = (const float4*)(kbase + jdx[2 * p]     * D_);
            const float4* kr1 = (const float4*)(kbase + jdx[2 * p + 1] * D_);
            float s0 = 0.f, s1 = 0.f, s2 = 0.f, s3 = 0.f;
            float s4 = 0.f, s5 = 0.f, s6 = 0.f, s7 = 0.f;
#pragma unroll 4
            for (int d4 = 0; d4 < D_ / 4; d4++) {
                float4 q4 = *(const float4*)(qrow + 4 * d4);   // 0.5*q broadcast
                float4 a4 = *(const float4*)(as   + 4 * d4);   // broadcast
                float4 ka = kr0[d4];                           // LDG.128 via L1
                float4 kb = kr1[d4];
                float u, t;
                u = fmaf(0.5f, ka.x, q4.x); t = tanh_approx(u); s0 = fmaf(a4.x, fmaf(u, t, u), s0);
                u = fmaf(0.5f, ka.y, q4.y); t = tanh_approx(u); s1 = fmaf(a4.y, fmaf(u, t, u), s1);
                u = fmaf(0.5f, ka.z, q4.z); t = tanh_approx(u); s2 = fmaf(a4.z, fmaf(u, t, u), s2);
                u = fmaf(0.5f, ka.w, q4.w); t = tanh_approx(u); s3 = fmaf(a4.w, fmaf(u, t, u), s3);
                u = fmaf(0.5f, kb.x, q4.x); t = tanh_approx(u); s4 = fmaf(a4.x, fmaf(u, t, u), s4);
                u = fmaf(0.5f, kb.y, q4.y); t = tanh_approx(u); s5 = fmaf(a4.y, fmaf(u, t, u), s5);
                u = fmaf(0.5f, kb.z, q4.z); t = tanh_approx(u); s6 = fmaf(a4.z, fmaf(u, t, u), s6);
                u = fmaf(0.5f, kb.w, q4.w); t = tanh_approx(u); s7 = fmaf(a4.w, fmaf(u, t, u), s7);
            }
            acc[2 * p]     = ((2 * p)     * 32 + lane < nkeep) ? ((s0 + s1) + (s2 + s3)) : -CUDART_INF_F;
            acc[2 * p + 1] = ((2 * p + 1) * 32 + lane < nkeep) ? ((s4 + s5) + (s6 + s7)) : -CUDART_INF_F;
        }
    }

    // ---- softmax over compacted values ----
    float mx = -CUDART_INF_F;
#pragma unroll
    for (int cc = 0; cc < NC; cc++) mx = fmaxf(mx, acc[cc]);
#pragma unroll
    for (int o = 16; o; o >>= 1) mx = fmaxf(mx, __shfl_xor_sync(0xffffffffu, mx, o));

    float sum = 0.f;
#pragma unroll
    for (int cc = 0; cc < NC; cc++) {
        float e = __expf(acc[cc] - mx);
        acc[cc] = e;
        sum += e;
    }
#pragma unroll
    for (int o = 16; o; o >>= 1) sum += __shfl_xor_sync(0xffffffffu, sum, o);
    float inv = (sum > 0.f) ? __fdividef(1.f, sum) : 0.f;

    // ---- scatter via warp-private smem stripe (no block barrier), dense store ----
    float* wsw = ws + warp * LK_;
#pragma unroll
    for (int c = 0; c < NC; c++) wsw[c * 32 + lane] = 0.f;
    __syncwarp();
#pragma unroll
    for (int cc = 0; cc < NC; cc++) {
        if (cc * 32 + lane < nkeep) wsw[jdx[cc]] = acc[cc] * inv;
    }
    __syncwarp();

    float* orow = out + ((size_t)bh * LQ_ + i) * LK_;
#pragma unroll
    for (int c = 0; c < NC; c++) orow[c * 32 + lane] = wsw[c * 32 + lane];
}

extern "C" void kernel_launch(void* const* d_in, const int* in_sizes, int n_in,
                              void* d_out, int out_size)
{
    const float* q   = (const float*)d_in[0];
    const float* k   = (const float*)d_in[1];
    const float* att = (const float*)d_in[2];
    const int*   m   = (const int*)d_in[3];
    float* out       = (float*)d_out;

    // floats: q 8*68 + a 64 + ws 8*384 = 3680 -> 14720 B; + idx16 8*384*2 = 6144 B
    const int smem_bytes = (ROWS * PAD + D_ + ROWS * LK_) * (int)sizeof(float)
                         + ROWS * LK_ * (int)sizeof(unsigned short);   // 20864
    cudaFuncSetAttribute(gatv2_kernel, cudaFuncAttributeMaxDynamicSharedMemorySize, smem_bytes);

    dim3 grid(B_ * H_ * (LQ_ / ROWS));   // 768
    gatv2_kernel<<<grid, 256, smem_bytes>>>(q, k, att, m, out);
}

// round 8
// speedup vs baseline: 1.5573x; 1.5573x over previous
#include <cuda_runtime.h>
#include <cuda_fp16.h>
#include <math_constants.h>

// GATv2 additive attention + masked softmax, mask-compacted v5 (fp16 K in smem).
// score(b,h,i,j) = sum_d a[h,d] * silu(q[b,h,i,d] + k[b,h,j,d])
// silu(s) = u*(1+tanh(u)), u=s/2; q,k pre-scaled by 0.5 at staging (k in fp16).
// Compacted gather from smem K rows (128B/row), fp32 math after unpack.

#define B_   2
#define H_   8
#define LQ_  384
#define LK_  384
#define D_   64
#define ROWS 8          // q rows per block, 1 warp per row
#define PAD  68         // q smem row stride (words)
#define NC   12         // LK/32 chunks

__device__ __forceinline__ float tanh_approx(float x) {
    float r;
    asm("tanh.approx.f32 %0, %1;" : "=f"(r) : "f"(x));
    return r;
}

__global__ __launch_bounds__(256, 2)
void gatv2_kernel(const float* __restrict__ q, const float* __restrict__ k,
                  const float* __restrict__ att, const int* __restrict__ mask,
                  float* __restrict__ out)
{
    extern __shared__ float smem[];
    // layout: K fp16 tile (uint4[384*8] = 49152B) | q fp32 | a | idx16
    uint4* ksu4 = (uint4*)smem;                       // [LK][8] 16B chunks, row = 128B
    float* qs   = (float*)(ksu4 + LK_ * 8);           // [ROWS][PAD] (0.5*q)
    float* as   = qs + ROWS * PAD;                    // [D]
    unsigned short* idxb = (unsigned short*)(as + D_);// [ROWS][LK]

    const int ntiles = LQ_ / ROWS;       // 48
    int blk   = blockIdx.x;
    int bh    = blk / ntiles;
    int itile = blk - bh * ntiles;
    int h     = bh & (H_ - 1);
    int tid   = threadIdx.x;
    int warp  = tid >> 5, lane = tid & 31;
    int i     = itile * ROWS + warp;

    // ---- stage 0.5*K tile as fp16: row j = 128 bytes ----
    const float4* kg = (const float4*)(k + (size_t)bh * LK_ * D_);
    for (int idxr = tid; idxr < LK_ * D_ / 4; idxr += 256) {
        int j = idxr >> 4, d4 = idxr & 15;
        float4 v = kg[idxr];
        __half2 h0 = __floats2half2_rn(0.5f * v.x, 0.5f * v.y);
        __half2 h1 = __floats2half2_rn(0.5f * v.z, 0.5f * v.w);
        uint2 w;
        *reinterpret_cast<__half2*>(&w.x) = h0;
        *reinterpret_cast<__half2*>(&w.y) = h1;
        *reinterpret_cast<uint2*>((char*)ksu4 + j * 128 + d4 * 8) = w;
    }
    // ---- stage 0.5*q rows (fp32) + a ----
    const float4* qg = (const float4*)(q + ((size_t)bh * LQ_ + itile * ROWS) * D_);
    for (int idxr = tid; idxr < ROWS * D_ / 4; idxr += 256) {
        int r = idxr >> 4, d4 = idxr & 15;
        float4 v = qg[idxr];
        v.x *= 0.5f; v.y *= 0.5f; v.z *= 0.5f; v.w *= 0.5f;
        *(float4*)(qs + r * PAD + d4 * 4) = v;
    }
    if (tid < D_) as[tid] = att[h * D_ + tid];

    // ---- mask ballot + compaction scatter (warp-private stripe) ----
    const int* mrow = mask + ((size_t)bh * LQ_ + i) * LK_;
    unsigned short* stripe = idxb + warp * LK_;
    int base = 0;
#pragma unroll
    for (int c = 0; c < NC; c++) {
        int j = c * 32 + lane;
        int keep = (mrow[j] == 0);
        unsigned b = __ballot_sync(0xffffffffu, keep);
        if (keep) stripe[base + __popc(b & ((1u << lane) - 1u))] = (unsigned short)j;
        base += __popc(b);
    }
    int nkeep  = base;
    int nchunk = (nkeep + 31) >> 5;

    __syncthreads();

    // ---- compacted indices to registers ----
    int jdx[NC];
#pragma unroll
    for (int cc = 0; cc < NC; cc++) {
        int slot = cc * 32 + lane;
        jdx[cc] = (slot < nkeep) ? (int)stripe[slot] : 0;
    }

    const float* qrow = qs + warp * PAD;
    float acc[NC];
#pragma unroll
    for (int cc = 0; cc < NC; cc++) acc[cc] = -CUDART_INF_F;

    // ---- chunk-pair score loop: fp16 K gather (8 x LDS.128 per row) ----
#pragma unroll
    for (int p = 0; p < NC / 2; p++) {
        if (2 * p < nchunk) {
            const uint4* kr0 = ksu4 + jdx[2 * p]     * 8;
            const uint4* kr1 = ksu4 + jdx[2 * p + 1] * 8;
            float s0 = 0.f, s1 = 0.f, s2 = 0.f, s3 = 0.f;
            float s4 = 0.f, s5 = 0.f, s6 = 0.f, s7 = 0.f;
#pragma unroll 2
            for (int c8 = 0; c8 < 8; c8++) {         // 8 d-values per iteration
                uint4 ka = kr0[c8];
                uint4 kb = kr1[c8];
                float4 qa = *(const float4*)(qrow + 8 * c8);
                float4 qb = *(const float4*)(qrow + 8 * c8 + 4);
                float4 aa = *(const float4*)(as   + 8 * c8);
                float4 ab = *(const float4*)(as   + 8 * c8 + 4);
                float2 f; float u, t;
                // row A, d = 8c8 .. 8c8+7
                f = __half22float2(*reinterpret_cast<const __half2*>(&ka.x));
                u = qa.x + f.x; t = tanh_approx(u); s0 = fmaf(aa.x, fmaf(u, t, u), s0);
                u = qa.y + f.y; t = tanh_approx(u); s1 = fmaf(aa.y, fmaf(u, t, u), s1);
                f = __half22float2(*reinterpret_cast<const __half2*>(&ka.y));
                u = qa.z + f.x; t = tanh_approx(u); s2 = fmaf(aa.z, fmaf(u, t, u), s2);
                u = qa.w + f.y; t = tanh_approx(u); s3 = fmaf(aa.w, fmaf(u, t, u), s3);
                f = __half22float2(*reinterpret_cast<const __half2*>(&ka.z));
                u = qb.x + f.x; t = tanh_approx(u); s0 = fmaf(ab.x, fmaf(u, t, u), s0);
                u = qb.y + f.y; t = tanh_approx(u); s1 = fmaf(ab.y, fmaf(u, t, u), s1);
                f = __half22float2(*reinterpret_cast<const __half2*>(&ka.w));
                u = qb.z + f.x; t = tanh_approx(u); s2 = fmaf(ab.z, fmaf(u, t, u), s2);
                u = qb.w + f.y; t = tanh_approx(u); s3 = fmaf(ab.w, fmaf(u, t, u), s3);
                // row B
                f = __half22float2(*reinterpret_cast<const __half2*>(&kb.x));
                u = qa.x + f.x; t = tanh_approx(u); s4 = fmaf(aa.x, fmaf(u, t, u), s4);
                u = qa.y + f.y; t = tanh_approx(u); s5 = fmaf(aa.y, fmaf(u, t, u), s5);
                f = __half22float2(*reinterpret_cast<const __half2*>(&kb.y));
                u = qa.z + f.x; t = tanh_approx(u); s6 = fmaf(aa.z, fmaf(u, t, u), s6);
                u = qa.w + f.y; t = tanh_approx(u); s7 = fmaf(aa.w, fmaf(u, t, u), s7);
                f = __half22float2(*reinterpret_cast<const __half2*>(&kb.z));
                u = qb.x + f.x; t = tanh_approx(u); s4 = fmaf(ab.x, fmaf(u, t, u), s4);
                u = qb.y + f.y; t = tanh_approx(u); s5 = fmaf(ab.y, fmaf(u, t, u), s5);
                f = __half22float2(*reinterpret_cast<const __half2*>(&kb.w));
                u = qb.z + f.x; t = tanh_approx(u); s6 = fmaf(ab.z, fmaf(u, t, u), s6);
                u = qb.w + f.y; t = tanh_approx(u); s7 = fmaf(ab.w, fmaf(u, t, u), s7);
            }
            acc[2 * p]     = ((2 * p)     * 32 + lane < nkeep) ? ((s0 + s1) + (s2 + s3)) : -CUDART_INF_F;
            acc[2 * p + 1] = ((2 * p + 1) * 32 + lane < nkeep) ? ((s4 + s5) + (s6 + s7)) : -CUDART_INF_F;
        }
    }

    // ---- softmax over compacted values ----
    float mx = -CUDART_INF_F;
#pragma unroll
    for (int cc = 0; cc < NC; cc++) mx = fmaxf(mx, acc[cc]);
#pragma unroll
    for (int o = 16; o; o >>= 1) mx = fmaxf(mx, __shfl_xor_sync(0xffffffffu, mx, o));

    float sum = 0.f;
#pragma unroll
    for (int cc = 0; cc < NC; cc++) {
        float e = __expf(acc[cc] - mx);
        acc[cc] = e;
        sum += e;
    }
#pragma unroll
    for (int o = 16; o; o >>= 1) sum += __shfl_xor_sync(0xffffffffu, sum, o);
    float inv = (sum > 0.f) ? __fdividef(1.f, sum) : 0.f;

    // ---- scatter via smem (reuse K region after barrier), dense store ----
    __syncthreads();                      // all warps done reading K tile
    float* ws = (float*)ksu4 + warp * LK_;
#pragma unroll
    for (int c = 0; c < NC; c++) ws[c * 32 + lane] = 0.f;
    __syncwarp();
#pragma unroll
    for (int cc = 0; cc < NC; cc++) {
        if (cc * 32 + lane < nkeep) ws[jdx[cc]] = acc[cc] * inv;
    }
    __syncwarp();

    float* orow = out + ((size_t)bh * LQ_ + i) * LK_;
#pragma unroll
    for (int c = 0; c < NC; c++) orow[c * 32 + lane] = ws[c * 32 + lane];
}

extern "C" void kernel_launch(void* const* d_in, const int* in_sizes, int n_in,
                              void* d_out, int out_size)
{
    const float* q   = (const float*)d_in[0];
    const float* k   = (const float*)d_in[1];
    const float* att = (const float*)d_in[2];
    const int*   m   = (const int*)d_in[3];
    float* out       = (float*)d_out;

    // K fp16 49152 + q 8*68*4 + a 256 + idx16 6144 = 57,728 B
    const int smem_bytes = LK_ * 128 + (ROWS * PAD + D_) * (int)sizeof(float)
                         + ROWS * LK_ * (int)sizeof(unsigned short);
    cudaFuncSetAttribute(gatv2_kernel, cudaFuncAttributeMaxDynamicSharedMemorySize, smem_bytes);

    dim3 grid(B_ * H_ * (LQ_ / ROWS));   // 768
    gatv2_kernel<<<grid, 256, smem_bytes>>>(q, k, att, m, out);
}

// round 9
// speedup vs baseline: 2.4666x; 1.5839x over previous
#include <cuda_runtime.h>
#include <cuda_fp16.h>
#include <math_constants.h>

// GATv2 additive attention + masked softmax, mask-compacted v6.
// fp16 K tile in smem with 144-BYTE row stride (16B-aligned, non-power-of-2
// -> gather LDS.128 start banks spread over 8 classes, ~7 phases, not 32).
// score(b,h,i,j) = sum_d a[h,d] * silu(q[b,h,i,d] + k[b,h,j,d])
// silu(s) = u*(1+tanh(u)), u=s/2; q,k pre-scaled by 0.5 (k stored fp16).

#define B_   2
#define H_   8
#define LQ_  384
#define LK_  384
#define D_   64
#define ROWS 8            // q rows per block, 1 warp per row
#define PAD  68           // q smem row stride (words)
#define NC   12           // LK/32 chunks
#define KSTR 144          // K smem row stride in BYTES (row data = 128B fp16)

__device__ __forceinline__ float tanh_approx(float x) {
    float r;
    asm("tanh.approx.f32 %0, %1;" : "=f"(r) : "f"(x));
    return r;
}

__global__ __launch_bounds__(256, 2)
void gatv2_kernel(const float* __restrict__ q, const float* __restrict__ k,
                  const float* __restrict__ att, const int* __restrict__ mask,
                  float* __restrict__ out)
{
    extern __shared__ float smem[];
    // layout: K fp16 tile (384*144B = 55296B) | q fp32 | a | idx16
    char*  ksb = (char*)smem;                          // [LK][KSTR]
    float* qs  = (float*)(ksb + LK_ * KSTR);           // [ROWS][PAD] (0.5*q)
    float* as  = qs + ROWS * PAD;                      // [D]
    unsigned short* idxb = (unsigned short*)(as + D_); // [ROWS][LK]

    const int ntiles = LQ_ / ROWS;       // 48
    int blk   = blockIdx.x;
    int bh    = blk / ntiles;
    int itile = blk - bh * ntiles;
    int h     = bh & (H_ - 1);
    int tid   = threadIdx.x;
    int warp  = tid >> 5, lane = tid & 31;
    int i     = itile * ROWS + warp;

    // ---- stage 0.5*K tile as fp16, 144B row stride ----
    const float4* kg = (const float4*)(k + (size_t)bh * LK_ * D_);
    for (int idxr = tid; idxr < LK_ * D_ / 4; idxr += 256) {
        int j = idxr >> 4, d4 = idxr & 15;
        float4 v = kg[idxr];
        __half2 h0 = __floats2half2_rn(0.5f * v.x, 0.5f * v.y);
        __half2 h1 = __floats2half2_rn(0.5f * v.z, 0.5f * v.w);
        uint2 w;
        *reinterpret_cast<__half2*>(&w.x) = h0;
        *reinterpret_cast<__half2*>(&w.y) = h1;
        *reinterpret_cast<uint2*>(ksb + j * KSTR + d4 * 8) = w;
    }
    // ---- stage 0.5*q rows (fp32) + a ----
    const float4* qg = (const float4*)(q + ((size_t)bh * LQ_ + itile * ROWS) * D_);
    for (int idxr = tid; idxr < ROWS * D_ / 4; idxr += 256) {
        int r = idxr >> 4, d4 = idxr & 15;
        float4 v = qg[idxr];
        v.x *= 0.5f; v.y *= 0.5f; v.z *= 0.5f; v.w *= 0.5f;
        *(float4*)(qs + r * PAD + d4 * 4) = v;
    }
    if (tid < D_) as[tid] = att[h * D_ + tid];

    // ---- mask ballot + compaction scatter (warp-private stripe) ----
    const int* mrow = mask + ((size_t)bh * LQ_ + i) * LK_;
    unsigned short* stripe = idxb + warp * LK_;
    int base = 0;
#pragma unroll
    for (int c = 0; c < NC; c++) {
        int j = c * 32 + lane;
        int keep = (mrow[j] == 0);
        unsigned b = __ballot_sync(0xffffffffu, keep);
        if (keep) stripe[base + __popc(b & ((1u << lane) - 1u))] = (unsigned short)j;
        base += __popc(b);
    }
    int nkeep  = base;
    int nchunk = (nkeep + 31) >> 5;

    __syncthreads();

    // ---- compacted indices to registers ----
    int jdx[NC];
#pragma unroll
    for (int cc = 0; cc < NC; cc++) {
        int slot = cc * 32 + lane;
        jdx[cc] = (slot < nkeep) ? (int)stripe[slot] : 0;
    }

    const float* qrow = qs + warp * PAD;
    float acc[NC];
#pragma unroll
    for (int cc = 0; cc < NC; cc++) acc[cc] = -CUDART_INF_F;

    // ---- chunk-pair score loop: fp16 K gather, 8 LDS.128 per row ----
#pragma unroll
    for (int p = 0; p < NC / 2; p++) {
        if (2 * p < nchunk) {
            const uint4* kr0 = (const uint4*)(ksb + jdx[2 * p]     * KSTR);
            const uint4* kr1 = (const uint4*)(ksb + jdx[2 * p + 1] * KSTR);
            float s0 = 0.f, s1 = 0.f, s2 = 0.f, s3 = 0.f;
            float s4 = 0.f, s5 = 0.f, s6 = 0.f, s7 = 0.f;
#pragma unroll 2
            for (int c8 = 0; c8 < 8; c8++) {         // 8 d-values per iteration
                uint4 ka = kr0[c8];
                uint4 kb = kr1[c8];
                float4 qa = *(const float4*)(qrow + 8 * c8);
                float4 qb = *(const float4*)(qrow + 8 * c8 + 4);
                float4 aa = *(const float4*)(as   + 8 * c8);
                float4 ab = *(const float4*)(as   + 8 * c8 + 4);
                float2 f; float u, t;
                f = __half22float2(*reinterpret_cast<const __half2*>(&ka.x));
                u = qa.x + f.x; t = tanh_approx(u); s0 = fmaf(aa.x, fmaf(u, t, u), s0);
                u = qa.y + f.y; t = tanh_approx(u); s1 = fmaf(aa.y, fmaf(u, t, u), s1);
                f = __half22float2(*reinterpret_cast<const __half2*>(&ka.y));
                u = qa.z + f.x; t = tanh_approx(u); s2 = fmaf(aa.z, fmaf(u, t, u), s2);
                u = qa.w + f.y; t = tanh_approx(u); s3 = fmaf(aa.w, fmaf(u, t, u), s3);
                f = __half22float2(*reinterpret_cast<const __half2*>(&ka.z));
                u = qb.x + f.x; t = tanh_approx(u); s0 = fmaf(ab.x, fmaf(u, t, u), s0);
                u = qb.y + f.y; t = tanh_approx(u); s1 = fmaf(ab.y, fmaf(u, t, u), s1);
                f = __half22float2(*reinterpret_cast<const __half2*>(&ka.w));
                u = qb.z + f.x; t = tanh_approx(u); s2 = fmaf(ab.z, fmaf(u, t, u), s2);
                u = qb.w + f.y; t = tanh_approx(u); s3 = fmaf(ab.w, fmaf(u, t, u), s3);
                f = __half22float2(*reinterpret_cast<const __half2*>(&kb.x));
                u = qa.x + f.x; t = tanh_approx(u); s4 = fmaf(aa.x, fmaf(u, t, u), s4);
                u = qa.y + f.y; t = tanh_approx(u); s5 = fmaf(aa.y, fmaf(u, t, u), s5);
                f = __half22float2(*reinterpret_cast<const __half2*>(&kb.y));
                u = qa.z + f.x; t = tanh_approx(u); s6 = fmaf(aa.z, fmaf(u, t, u), s6);
                u = qa.w + f.y; t = tanh_approx(u); s7 = fmaf(aa.w, fmaf(u, t, u), s7);
                f = __half22float2(*reinterpret_cast<const __half2*>(&kb.z));
                u = qb.x + f.x; t = tanh_approx(u); s4 = fmaf(ab.x, fmaf(u, t, u), s4);
                u = qb.y + f.y; t = tanh_approx(u); s5 = fmaf(ab.y, fmaf(u, t, u), s5);
                f = __half22float2(*reinterpret_cast<const __half2*>(&kb.w));
                u = qb.z + f.x; t = tanh_approx(u); s6 = fmaf(ab.z, fmaf(u, t, u), s6);
                u = qb.w + f.y; t = tanh_approx(u); s7 = fmaf(ab.w, fmaf(u, t, u), s7);
            }
            acc[2 * p]     = ((2 * p)     * 32 + lane < nkeep) ? ((s0 + s1) + (s2 + s3)) : -CUDART_INF_F;
            acc[2 * p + 1] = ((2 * p + 1) * 32 + lane < nkeep) ? ((s4 + s5) + (s6 + s7)) : -CUDART_INF_F;
        }
    }

    // ---- softmax over compacted values ----
    float mx = -CUDART_INF_F;
#pragma unroll
    for (int cc = 0; cc < NC; cc++) mx = fmaxf(mx, acc[cc]);
#pragma unroll
    for (int o = 16; o; o >>= 1) mx = fmaxf(mx, __shfl_xor_sync(0xffffffffu, mx, o));

    float sum = 0.f;
#pragma unroll
    for (int cc = 0; cc < NC; cc++) {
        float e = __expf(acc[cc] - mx);
        acc[cc] = e;
        sum += e;
    }
#pragma unroll
    for (int o = 16; o; o >>= 1) sum += __shfl_xor_sync(0xffffffffu, sum, o);
    float inv = (sum > 0.f) ? __fdividef(1.f, sum) : 0.f;

    // ---- scatter via smem (reuse K region after barrier), dense store ----
    __syncthreads();                      // all warps done reading K tile
    float* ws = (float*)ksb + warp * LK_;
#pragma unroll
    for (int c = 0; c < NC; c++) ws[c * 32 + lane] = 0.f;
    __syncwarp();
#pragma unroll
    for (int cc = 0; cc < NC; cc++) {
        if (cc * 32 + lane < nkeep) ws[jdx[cc]] = acc[cc] * inv;
    }
    __syncwarp();

    float* orow = out + ((size_t)bh * LQ_ + i) * LK_;
#pragma unroll
    for (int c = 0; c < NC; c++) orow[c * 32 + lane] = ws[c * 32 + lane];
}

extern "C" void kernel_launch(void* const* d_in, const int* in_sizes, int n_in,
                              void* d_out, int out_size)
{
    const float* q   = (const float*)d_in[0];
    const float* k   = (const float*)d_in[1];
    const float* att = (const float*)d_in[2];
    const int*   m   = (const int*)d_in[3];
    float* out       = (float*)d_out;

    // K fp16 384*144 = 55296 + q 2176 + a 256 + idx16 6144 = 63,872 B
    const int smem_bytes = LK_ * KSTR + (ROWS * PAD + D_) * (int)sizeof(float)
                         + ROWS * LK_ * (int)sizeof(unsigned short);
    cudaFuncSetAttribute(gatv2_kernel, cudaFuncAttributeMaxDynamicSharedMemorySize, smem_bytes);

    dim3 grid(B_ * H_ * (LQ_ / ROWS));   // 768
    gatv2_kernel<<<grid, 256, smem_bytes>>>(q, k, att, m, out);
}